// round 1
// baseline (speedup 1.0000x reference)
#include <cuda_runtime.h>
#include <cstdint>

// Problem constants (fixed by setup_inputs)
#define NROW 8192
#define LATENT 128
#define HID 32
#define MSG 64
#define THRESH 1.5f

// Scratch (device globals: no allocation allowed)
__device__ float g_h[NROW * HID];     // 1 MB
__device__ float g_msg[NROW * MSG];   // 2 MB
__device__ float g_gum[NROW * MSG];   // 2 MB
__device__ float g_S[MSG];            // column sums of messages

// ---------------------------------------------------------------------------
// threefry2x32 (JAX/Random123), key = (0, 42)
// ---------------------------------------------------------------------------
__device__ __forceinline__ uint32_t rotl32(uint32_t x, int r) {
    return __funnelshift_l(x, x, r);
}

__device__ __forceinline__ void threefry2x32_042(uint32_t x0, uint32_t x1,
                                                 uint32_t& o0, uint32_t& o1) {
    const uint32_t k0 = 0u, k1 = 42u;
    const uint32_t k2 = 0u ^ 42u ^ 0x1BD11BDAu;
    x0 += k0; x1 += k1;
#define TF_RND(r) { x0 += x1; x1 = rotl32(x1, r); x1 ^= x0; }
    TF_RND(13) TF_RND(15) TF_RND(26) TF_RND(6)
    x0 += k1; x1 += k2 + 1u;
    TF_RND(17) TF_RND(29) TF_RND(16) TF_RND(24)
    x0 += k2; x1 += k0 + 2u;
    TF_RND(13) TF_RND(15) TF_RND(26) TF_RND(6)
    x0 += k0; x1 += k1 + 3u;
    TF_RND(17) TF_RND(29) TF_RND(16) TF_RND(24)
    x0 += k1; x1 += k2 + 4u;
    TF_RND(13) TF_RND(15) TF_RND(26) TF_RND(6)
    x0 += k2; x1 += k0 + 5u;
#undef TF_RND
    o0 = x0; o1 = x1;
}

__device__ __forceinline__ float gumbel_from_bits(uint32_t bits) {
    // jax.random.uniform(key, ..., 1e-10, 1.0) for f32:
    float u = __uint_as_float((bits >> 9) | 0x3f800000u) - 1.0f;
    u = u * (1.0f - 1e-10f) + 1e-10f;   // (maxval-minval) rounds to 1.0f in fp32
    u = fmaxf(1e-10f, u);
    return -logf(-logf(u));
}

// ---------------------------------------------------------------------------
// K0: zero the column-sum accumulator
// ---------------------------------------------------------------------------
__global__ void k0_zero() {
    if (threadIdx.x < MSG) g_S[threadIdx.x] = 0.0f;
}

// ---------------------------------------------------------------------------
// K1: h = relu(z @ enc_W + enc_b); messages = h @ msg_W + msg_b; S += col-sums
// 8 rows per 256-thread block. messages stored so that float2 index
// [row*32 + c] holds columns (2c, 2c+1).
// ---------------------------------------------------------------------------
__global__ __launch_bounds__(256) void k1_enc(
    const float* __restrict__ z,
    const float* __restrict__ encW, const float* __restrict__ encb,
    const float* __restrict__ msgW, const float* __restrict__ msgb)
{
    __shared__ float  z_s[8 * LATENT];
    __shared__ float  h_s[8 * HID];
    __shared__ float2 m_s[8 * 32];

    const int t  = threadIdx.x;
    const int i0 = blockIdx.x * 8;

    // load 8 rows of z (1024 floats = 256 float4)
    reinterpret_cast<float4*>(z_s)[t] =
        reinterpret_cast<const float4*>(z + (size_t)i0 * LATENT)[t];
    __syncthreads();

    const int r = t >> 5, c = t & 31;

    float a = encb[c];
#pragma unroll 8
    for (int k = 0; k < LATENT; ++k)
        a = fmaf(z_s[r * LATENT + k], encW[k * HID + c], a);
    a = fmaxf(a, 0.0f);
    h_s[r * HID + c] = a;
    g_h[(size_t)(i0 + r) * HID + c] = a;
    __syncthreads();

    float2 m = make_float2(msgb[2 * c], msgb[2 * c + 1]);
#pragma unroll
    for (int k = 0; k < HID; ++k) {
        float hk = h_s[r * HID + k];
        float2 w = reinterpret_cast<const float2*>(msgW)[k * 32 + c];
        m.x = fmaf(hk, w.x, m.x);
        m.y = fmaf(hk, w.y, m.y);
    }
    reinterpret_cast<float2*>(g_msg)[(size_t)(i0 + r) * 32 + c] = m;
    m_s[r * 32 + c] = m;
    __syncthreads();

    if (t < MSG) {
        float s = 0.0f;
#pragma unroll
        for (int rr = 0; rr < 8; ++rr) {
            float2 mm = m_s[rr * 32 + (t >> 1)];
            s += (t & 1) ? mm.y : mm.x;
        }
        atomicAdd(&g_S[t], s);
    }
}

// ---------------------------------------------------------------------------
// Kg: gumbel noise via partitionable threefry:
//     bits[i] = o0 ^ o1, (o0,o1) = threefry2x32((0,42), (hi32(i)=0, lo32(i)=i))
// ---------------------------------------------------------------------------
__global__ __launch_bounds__(256) void kg_gumbel() {
    const uint32_t i = blockIdx.x * 256u + threadIdx.x;   // < NROW*MSG = 524288
    uint32_t o0, o1;
    threefry2x32_042(0u, i, o0, o1);
    g_gum[i] = gumbel_from_bits(o0 ^ o1);
}

// ---------------------------------------------------------------------------
// K2: masked aggregation via complement + fused tail (h2, logits, softmax).
// 128 CTAs x 512 threads; CTA owns 64 rows (4 per warp); 64 column tiles of 128.
// Lane l accumulates message columns (2l, 2l+1) as float2.
// ---------------------------------------------------------------------------
#define CTILE 128
#define ROWS_PER_CTA 64
#define TPB2 512

__global__ __launch_bounds__(TPB2) void k2_main(
    const float* __restrict__ dists, const float* __restrict__ tau,
    const float* __restrict__ updW,  const float* __restrict__ updb,
    const float* __restrict__ outW,  const float* __restrict__ outb,
    float* __restrict__ out)
{
    __shared__ float msg_s[CTILE * MSG];   // 32 KB

    const int warp = threadIdx.x >> 5;
    const int lane = threadIdx.x & 31;
    const int row0 = blockIdx.x * ROWS_PER_CTA + warp * 4;

    float2 acc[4];
#pragma unroll
    for (int r = 0; r < 4; ++r) acc[r] = make_float2(0.0f, 0.0f);

#pragma unroll 1
    for (int t = 0; t < NROW / CTILE; ++t) {
        __syncthreads();
        {
            const float4* src = reinterpret_cast<const float4*>(g_msg) + t * (CTILE * MSG / 4);
            float4* dst = reinterpret_cast<float4*>(msg_s);
#pragma unroll
            for (int q = 0; q < CTILE * MSG / 4 / TPB2; ++q)   // 4 iters
                dst[threadIdx.x + q * TPB2] = src[threadIdx.x + q * TPB2];
        }
        __syncthreads();

        const int jb = t * CTILE;
        const float2* ms = reinterpret_cast<const float2*>(msg_s);
#pragma unroll
        for (int r = 0; r < 4; ++r) {
            const float4 d4 = *reinterpret_cast<const float4*>(
                dists + (size_t)(row0 + r) * NROW + jb + lane * 4);
            unsigned m0 = __ballot_sync(0xffffffffu, d4.x >= THRESH);
            unsigned m1 = __ballot_sync(0xffffffffu, d4.y >= THRESH);
            unsigned m2 = __ballot_sync(0xffffffffu, d4.z >= THRESH);
            unsigned m3 = __ballot_sync(0xffffffffu, d4.w >= THRESH);
            while (m0) { int b = __ffs(m0) - 1; m0 &= m0 - 1;
                float2 v = ms[(b * 4 + 0) * 32 + lane]; acc[r].x += v.x; acc[r].y += v.y; }
            while (m1) { int b = __ffs(m1) - 1; m1 &= m1 - 1;
                float2 v = ms[(b * 4 + 1) * 32 + lane]; acc[r].x += v.x; acc[r].y += v.y; }
            while (m2) { int b = __ffs(m2) - 1; m2 &= m2 - 1;
                float2 v = ms[(b * 4 + 2) * 32 + lane]; acc[r].x += v.x; acc[r].y += v.y; }
            while (m3) { int b = __ffs(m3) - 1; m3 &= m3 - 1;
                float2 v = ms[(b * 4 + 3) * 32 + lane]; acc[r].x += v.x; acc[r].y += v.y; }
        }
    }

    // ---- fused tail, one row at a time within the warp ----
    const float itau = 1.0f / tau[0];
    const float S0 = g_S[2 * lane], S1 = g_S[2 * lane + 1];

#pragma unroll 1
    for (int r = 0; r < 4; ++r) {
        const int row = row0 + r;
        const float dii = dists[(size_t)row * NROW + row];
        const float2 mi = reinterpret_cast<const float2*>(g_msg)[(size_t)row * 32 + lane];
        const float sub = (dii < THRESH) ? 1.0f : 0.0f;

        // aggregated[2l], aggregated[2l+1]
        const float a0 = S0 - acc[r].x - sub * mi.x;
        const float a1 = S1 - acc[r].y - sub * mi.y;

        const float h_own = g_h[(size_t)row * HID + lane];   // h[row][lane]

        // h2[lane] = relu( sum_k h[k]*W[k][lane] + sum_k agg[k]*W[32+k][lane] )
        float acc2 = updb[lane];
#pragma unroll
        for (int k = 0; k < 32; ++k) {
            const float hk = __shfl_sync(0xffffffffu, h_own, k);
            const float src = (k & 1) ? a1 : a0;
            const float gA = __shfl_sync(0xffffffffu, src, k >> 1);         // agg[k]
            const float gB = __shfl_sync(0xffffffffu, src, 16 + (k >> 1));  // agg[32+k]
            acc2 = fmaf(hk, updW[k * HID + lane], acc2);
            acc2 = fmaf(gA, updW[(32 + k) * HID + lane], acc2);
            acc2 = fmaf(gB, updW[(64 + k) * HID + lane], acc2);
        }
        const float h2v = fmaxf(acc2, 0.0f);

        // logits[2l], logits[2l+1]
        float2 lg = make_float2(outb[2 * lane], outb[2 * lane + 1]);
#pragma unroll
        for (int k = 0; k < 32; ++k) {
            const float h2k = __shfl_sync(0xffffffffu, h2v, k);
            const float2 w = reinterpret_cast<const float2*>(outW)[k * 32 + lane];
            lg.x = fmaf(h2k, w.x, lg.x);
            lg.y = fmaf(h2k, w.y, lg.y);
        }

        const float2 gum = reinterpret_cast<const float2*>(g_gum)[(size_t)row * 32 + lane];
        const float v0 = (lg.x + gum.x) * itau;
        const float v1 = (lg.y + gum.y) * itau;

        // softmax over 64 values held 2-per-lane
        float mx = fmaxf(v0, v1);
#pragma unroll
        for (int o = 16; o; o >>= 1) mx = fmaxf(mx, __shfl_xor_sync(0xffffffffu, mx, o));
        const float e0 = expf(v0 - mx), e1 = expf(v1 - mx);
        float s = e0 + e1;
#pragma unroll
        for (int o = 16; o; o >>= 1) s += __shfl_xor_sync(0xffffffffu, s, o);
        const float inv = 1.0f / s;

        reinterpret_cast<float2*>(out)[(size_t)row * 32 + lane] =
            make_float2(e0 * inv, e1 * inv);
    }
}

// ---------------------------------------------------------------------------
extern "C" void kernel_launch(void* const* d_in, const int* in_sizes, int n_in,
                              void* d_out, int out_size) {
    const float* z    = (const float*)d_in[0];
    const float* tau  = (const float*)d_in[1];
    const float* dist = (const float*)d_in[2];
    const float* encW = (const float*)d_in[3];
    const float* encb = (const float*)d_in[4];
    const float* msgW = (const float*)d_in[5];
    const float* msgb = (const float*)d_in[6];
    const float* updW = (const float*)d_in[7];
    const float* updb = (const float*)d_in[8];
    const float* outW = (const float*)d_in[9];
    const float* outb = (const float*)d_in[10];
    float* out = (float*)d_out;

    k0_zero<<<1, 64>>>();
    k1_enc<<<NROW / 8, 256>>>(z, encW, encb, msgW, msgb);
    kg_gumbel<<<(NROW * MSG) / 256, 256>>>();
    k2_main<<<NROW / ROWS_PER_CTA, TPB2>>>(dist, tau, updW, updb, outW, outb, out);
}

// round 3
// speedup vs baseline: 1.9306x; 1.9306x over previous
#include <cuda_runtime.h>
#include <cstdint>

#define NROW 8192
#define LATENT 128
#define HID 32
#define MSG 64
#define THRESH 1.5f

#define NCB 4                 // column blocks
#define COLB (NROW / NCB)     // 2048 cols per CTA
#define CTILE 128             // cols per smem tile
#define NT (COLB / CTILE)     // 16 tiles
#define TPB2 512

// ---------------- device scratch (no allocation allowed) -------------------
__device__ __align__(16) float g_h[NROW * HID];          // 1 MB
__device__ __align__(16) float g_msgF[NROW * MSG];       // 2 MB row-major
__device__ __align__(16) float g_gum[NROW * MSG];        // 2 MB
__device__ __align__(16) float g_part[NCB * NROW * MSG]; // 8 MB fail-sum partials
__device__ float g_S[MSG];                               // column sums of messages

// ---------------- cp.async helpers -----------------------------------------
__device__ __forceinline__ uint32_t smem_u32(const void* p) {
    uint32_t a;
    asm("{ .reg .u64 t; cvta.to.shared.u64 t, %1; cvt.u32.u64 %0, t; }" : "=r"(a) : "l"(p));
    return a;
}
#define CP_ASYNC16(sm, gp) \
    asm volatile("cp.async.cg.shared.global [%0], [%1], 16;" :: "r"(sm), "l"(gp) : "memory")
#define CP_COMMIT() asm volatile("cp.async.commit_group;" ::: "memory")
#define CP_WAIT0()  asm volatile("cp.async.wait_group 0;" ::: "memory")

// ---------------- threefry / gumbel ----------------------------------------
__device__ __forceinline__ uint32_t rotl32(uint32_t x, int r) { return __funnelshift_l(x, x, r); }
__device__ __forceinline__ void threefry2x32_042(uint32_t x0, uint32_t x1,
                                                 uint32_t& o0, uint32_t& o1) {
    const uint32_t k0 = 0u, k1 = 42u, k2 = 0u ^ 42u ^ 0x1BD11BDAu;
    x0 += k0; x1 += k1;
#define TF_RND(r) { x0 += x1; x1 = rotl32(x1, r); x1 ^= x0; }
    TF_RND(13) TF_RND(15) TF_RND(26) TF_RND(6)
    x0 += k1; x1 += k2 + 1u;
    TF_RND(17) TF_RND(29) TF_RND(16) TF_RND(24)
    x0 += k2; x1 += k0 + 2u;
    TF_RND(13) TF_RND(15) TF_RND(26) TF_RND(6)
    x0 += k0; x1 += k1 + 3u;
    TF_RND(17) TF_RND(29) TF_RND(16) TF_RND(24)
    x0 += k1; x1 += k2 + 4u;
    TF_RND(13) TF_RND(15) TF_RND(26) TF_RND(6)
    x0 += k2; x1 += k0 + 5u;
#undef TF_RND
    o0 = x0; o1 = x1;
}

__global__ __launch_bounds__(256) void kg_gumbel() {
    const uint32_t i = blockIdx.x * 256u + threadIdx.x;
    uint32_t o0, o1;
    threefry2x32_042(0u, i, o0, o1);
    const uint32_t bits = o0 ^ o1;
    float u = __uint_as_float((bits >> 9) | 0x3f800000u) - 1.0f;
    u = u * (1.0f - 1e-10f) + 1e-10f;
    u = fmaxf(1e-10f, u);
    g_gum[i] = -logf(-logf(u));
}

// ---------------- K0: zero column-sum accumulator ---------------------------
__global__ void k0_zero() {
    if (threadIdx.x < MSG) g_S[threadIdx.x] = 0.0f;
}

// ---------------- K1: h = relu(z@encW+b); msg = h@msgW+b; S += colsum -------
__global__ __launch_bounds__(256) void k1_enc(
    const float* __restrict__ z,
    const float* __restrict__ encW, const float* __restrict__ encb,
    const float* __restrict__ msgW, const float* __restrict__ msgb)
{
    __shared__ float  z_s[8 * LATENT];
    __shared__ float  h_s[8 * HID];
    __shared__ float2 m_s[8 * 32];

    const int t  = threadIdx.x;
    const int i0 = blockIdx.x * 8;

    reinterpret_cast<float4*>(z_s)[t] =
        reinterpret_cast<const float4*>(z + (size_t)i0 * LATENT)[t];
    __syncthreads();

    const int r = t >> 5, c = t & 31;

    float a = encb[c];
#pragma unroll 8
    for (int k = 0; k < LATENT; ++k)
        a = fmaf(z_s[r * LATENT + k], encW[k * HID + c], a);
    a = fmaxf(a, 0.0f);
    h_s[r * HID + c] = a;
    g_h[(size_t)(i0 + r) * HID + c] = a;
    __syncthreads();

    float2 m = make_float2(msgb[2 * c], msgb[2 * c + 1]);
#pragma unroll
    for (int k = 0; k < HID; ++k) {
        float hk = h_s[r * HID + k];
        float2 w = reinterpret_cast<const float2*>(msgW)[k * 32 + c];
        m.x = fmaf(hk, w.x, m.x);
        m.y = fmaf(hk, w.y, m.y);
    }
    reinterpret_cast<float2*>(g_msgF)[(size_t)(i0 + r) * 32 + c] = m;
    m_s[r * 32 + c] = m;
    __syncthreads();

    if (t < MSG) {
        float s = 0.0f;
#pragma unroll
        for (int rr = 0; rr < 8; ++rr) {
            float2 mm = m_s[rr * 32 + (t >> 1)];
            s += (t & 1) ? mm.y : mm.x;
        }
        atomicAdd(&g_S[t], s);
    }
}

// ---------------- K2: fail-sum partials, 2D grid (rowblk x colblk) ----------
// CTA = 64 rows x 2048 cols. 16 warps, 4 rows/warp. Double-buffered msg tile.
__global__ __launch_bounds__(TPB2, 2) void k2_agg(const float* __restrict__ dists)
{
    extern __shared__ float msg_s[];          // 2 x 128*64 floats = 64KB

    const int tid  = threadIdx.x;
    const int wid  = tid >> 5;
    const int lane = tid & 31;
    const int rb   = blockIdx.x;              // 0..127
    const int cb   = blockIdx.y;              // 0..3
    const int row0 = rb * 64 + wid * 4;
    const int col0 = cb * COLB;

    // per-row dist pointers (advance by CTILE per tile)
    const float* d0 = dists + (size_t)(row0 + 0) * NROW + col0 + lane * 4;
    const float* d1 = d0 + NROW;
    const float* d2 = d1 + NROW;
    const float* d3 = d2 + NROW;

    float2 acc[4];
#pragma unroll
    for (int r = 0; r < 4; ++r) acc[r] = make_float2(0.0f, 0.0f);

    const uint32_t sm0 = smem_u32(msg_s);

    // prefetch tile 0 into buffer 0
    {
        const float4* src = reinterpret_cast<const float4*>(g_msgF + (size_t)col0 * MSG);
#pragma unroll
        for (int q = 0; q < 4; ++q)
            CP_ASYNC16(sm0 + (tid + q * TPB2) * 16, src + tid + q * TPB2);
        CP_COMMIT();
    }

#pragma unroll 1
    for (int t = 0; t < NT; ++t) {
        const int s = t & 1;
        CP_WAIT0();
        __syncthreads();
        if (t + 1 < NT) {
            const uint32_t dst = sm0 + ((s ^ 1) * CTILE * MSG) * 4;
            const float4* src = reinterpret_cast<const float4*>(
                g_msgF + (size_t)(col0 + (t + 1) * CTILE) * MSG);
#pragma unroll
            for (int q = 0; q < 4; ++q)
                CP_ASYNC16(dst + (tid + q * TPB2) * 16, src + tid + q * TPB2);
            CP_COMMIT();
        }

        const float2* mf = reinterpret_cast<const float2*>(msg_s + s * CTILE * MSG) + lane;
        const int ofs = t * CTILE;

#define ROW_TILE(r, dp) { \
        const float4 d4 = *reinterpret_cast<const float4*>(dp + ofs);                 \
        unsigned m0 = __ballot_sync(0xffffffffu, d4.x >= THRESH);                     \
        unsigned m1 = __ballot_sync(0xffffffffu, d4.y >= THRESH);                     \
        unsigned m2 = __ballot_sync(0xffffffffu, d4.z >= THRESH);                     \
        unsigned m3 = __ballot_sync(0xffffffffu, d4.w >= THRESH);                     \
        while (m0) { int b = __ffs(m0) - 1; m0 &= m0 - 1;                             \
            float2 v = mf[(unsigned)(4 * b + 0) * 32u];                               \
            acc[r].x += v.x; acc[r].y += v.y; }                                       \
        while (m1) { int b = __ffs(m1) - 1; m1 &= m1 - 1;                             \
            float2 v = mf[(unsigned)(4 * b + 1) * 32u];                               \
            acc[r].x += v.x; acc[r].y += v.y; }                                       \
        while (m2) { int b = __ffs(m2) - 1; m2 &= m2 - 1;                             \
            float2 v = mf[(unsigned)(4 * b + 2) * 32u];                               \
            acc[r].x += v.x; acc[r].y += v.y; }                                       \
        while (m3) { int b = __ffs(m3) - 1; m3 &= m3 - 1;                             \
            float2 v = mf[(unsigned)(4 * b + 3) * 32u];                               \
            acc[r].x += v.x; acc[r].y += v.y; } }

        ROW_TILE(0, d0)
        ROW_TILE(1, d1)
        ROW_TILE(2, d2)
        ROW_TILE(3, d3)
#undef ROW_TILE
    }

    // write partial fail-sums: plane cb, rows row0..row0+3
    float2* gp = reinterpret_cast<float2*>(g_part) +
                 ((size_t)cb * NROW + row0) * 32 + lane;
#pragma unroll
    for (int r = 0; r < 4; ++r) gp[r * 32] = acc[r];
}

// ---------------- K3: combine partials + fused tail --------------------------
// 64 CTAs x 512 thr; 16 warps x 8 rows. Lane owns output cols (2l, 2l+1).
__global__ __launch_bounds__(TPB2) void k3_tail(
    const float* __restrict__ dists, const float* __restrict__ tau,
    const float* __restrict__ updW,  const float* __restrict__ updb,
    const float* __restrict__ outW,  const float* __restrict__ outb,
    float* __restrict__ out)
{
    const int wid  = threadIdx.x >> 5;
    const int lane = threadIdx.x & 31;
    const float itau = 1.0f / tau[0];
    const float S0 = g_S[2 * lane], S1 = g_S[2 * lane + 1];

#pragma unroll 1
    for (int rr = 0; rr < 8; ++rr) {
        const size_t row = (size_t)blockIdx.x * 128 + wid * 8 + rr;

        const float dii = dists[row * NROW + row];
        const float sub = (dii < THRESH) ? 1.0f : 0.0f;
        const float2 mi = reinterpret_cast<const float2*>(g_msgF)[row * 32 + lane];

        float a0 = S0 - sub * mi.x;
        float a1 = S1 - sub * mi.y;
#pragma unroll
        for (int p = 0; p < NCB; ++p) {
            const float2 pv = reinterpret_cast<const float2*>(g_part)
                [((size_t)p * NROW + row) * 32 + lane];
            a0 -= pv.x; a1 -= pv.y;
        }

        const float h_own = g_h[row * HID + lane];

        float acc2 = updb[lane];
#pragma unroll
        for (int k = 0; k < 32; ++k) {
            const float hk = __shfl_sync(0xffffffffu, h_own, k);
            const float src = (k & 1) ? a1 : a0;
            const float gA = __shfl_sync(0xffffffffu, src, k >> 1);
            const float gB = __shfl_sync(0xffffffffu, src, 16 + (k >> 1));
            acc2 = fmaf(hk, updW[k * HID + lane], acc2);
            acc2 = fmaf(gA, updW[(32 + k) * HID + lane], acc2);
            acc2 = fmaf(gB, updW[(64 + k) * HID + lane], acc2);
        }
        const float h2v = fmaxf(acc2, 0.0f);

        float2 lg = make_float2(outb[2 * lane], outb[2 * lane + 1]);
#pragma unroll
        for (int k = 0; k < 32; ++k) {
            const float h2k = __shfl_sync(0xffffffffu, h2v, k);
            const float2 w = reinterpret_cast<const float2*>(outW)[k * 32 + lane];
            lg.x = fmaf(h2k, w.x, lg.x);
            lg.y = fmaf(h2k, w.y, lg.y);
        }

        const float2 gum = reinterpret_cast<const float2*>(g_gum)[row * 32 + lane];
        const float v0 = (lg.x + gum.x) * itau;
        const float v1 = (lg.y + gum.y) * itau;

        float mx = fmaxf(v0, v1);
#pragma unroll
        for (int o = 16; o; o >>= 1) mx = fmaxf(mx, __shfl_xor_sync(0xffffffffu, mx, o));
        const float e0 = expf(v0 - mx), e1 = expf(v1 - mx);
        float sm = e0 + e1;
#pragma unroll
        for (int o = 16; o; o >>= 1) sm += __shfl_xor_sync(0xffffffffu, sm, o);
        const float inv = 1.0f / sm;

        reinterpret_cast<float2*>(out)[row * 32 + lane] = make_float2(e0 * inv, e1 * inv);
    }
}

// ---------------------------------------------------------------------------
extern "C" void kernel_launch(void* const* d_in, const int* in_sizes, int n_in,
                              void* d_out, int out_size) {
    const float* z    = (const float*)d_in[0];
    const float* tau  = (const float*)d_in[1];
    const float* dist = (const float*)d_in[2];
    const float* encW = (const float*)d_in[3];
    const float* encb = (const float*)d_in[4];
    const float* msgW = (const float*)d_in[5];
    const float* msgb = (const float*)d_in[6];
    const float* updW = (const float*)d_in[7];
    const float* updb = (const float*)d_in[8];
    const float* outW = (const float*)d_in[9];
    const float* outb = (const float*)d_in[10];
    float* out = (float*)d_out;

    const int smem2 = 2 * CTILE * MSG * (int)sizeof(float);   // 64 KB
    cudaFuncSetAttribute(k2_agg, cudaFuncAttributeMaxDynamicSharedMemorySize, smem2);

    k0_zero<<<1, 64>>>();
    k1_enc<<<NROW / 8, 256>>>(z, encW, encb, msgW, msgb);
    kg_gumbel<<<(NROW * MSG) / 256, 256>>>();

    dim3 g2(NROW / 64, NCB);
    k2_agg<<<g2, TPB2, smem2>>>(dist);

    k3_tail<<<NROW / 128, TPB2>>>(dist, tau, updW, updb, outW, outb, out);
}

// round 4
// speedup vs baseline: 2.3911x; 1.2385x over previous
#include <cuda_runtime.h>
#include <cstdint>

#define NROW 8192
#define LATENT 128
#define HID 32
#define MSG 64
#define THRESH 1.5f

#define NCB 16                // column blocks
#define COLB (NROW / NCB)     // 512 cols per CTA
#define CTILE 128             // cols per smem tile
#define NT (COLB / CTILE)     // 4 tiles
#define TPB2 512

// ---------------- device scratch (no allocation allowed) -------------------
__device__ __align__(16) float g_h[NROW * HID];          // 1 MB
__device__ __align__(16) float g_msgF[NROW * MSG];       // 2 MB row-major
__device__ __align__(16) float g_gum[NROW * MSG];        // 2 MB
__device__ __align__(16) float g_part[NCB * NROW * MSG]; // 32 MB fail-sum partials
__device__ float g_S[MSG];                               // column sums of messages

// ---------------- cp.async helpers -----------------------------------------
__device__ __forceinline__ uint32_t smem_u32(const void* p) {
    uint32_t a;
    asm("{ .reg .u64 t; cvta.to.shared.u64 t, %1; cvt.u32.u64 %0, t; }" : "=r"(a) : "l"(p));
    return a;
}
#define CP_ASYNC16(sm, gp) \
    asm volatile("cp.async.cg.shared.global [%0], [%1], 16;" :: "r"(sm), "l"(gp) : "memory")
#define CP_COMMIT() asm volatile("cp.async.commit_group;" ::: "memory")
#define CP_WAIT0()  asm volatile("cp.async.wait_group 0;" ::: "memory")

// ---------------- threefry / gumbel ----------------------------------------
__device__ __forceinline__ uint32_t rotl32(uint32_t x, int r) { return __funnelshift_l(x, x, r); }
__device__ __forceinline__ void threefry2x32_042(uint32_t x0, uint32_t x1,
                                                 uint32_t& o0, uint32_t& o1) {
    const uint32_t k0 = 0u, k1 = 42u, k2 = 0u ^ 42u ^ 0x1BD11BDAu;
    x0 += k0; x1 += k1;
#define TF_RND(r) { x0 += x1; x1 = rotl32(x1, r); x1 ^= x0; }
    TF_RND(13) TF_RND(15) TF_RND(26) TF_RND(6)
    x0 += k1; x1 += k2 + 1u;
    TF_RND(17) TF_RND(29) TF_RND(16) TF_RND(24)
    x0 += k2; x1 += k0 + 2u;
    TF_RND(13) TF_RND(15) TF_RND(26) TF_RND(6)
    x0 += k0; x1 += k1 + 3u;
    TF_RND(17) TF_RND(29) TF_RND(16) TF_RND(24)
    x0 += k1; x1 += k2 + 4u;
    TF_RND(13) TF_RND(15) TF_RND(26) TF_RND(6)
    x0 += k2; x1 += k0 + 5u;
#undef TF_RND
    o0 = x0; o1 = x1;
}

__global__ __launch_bounds__(256) void kg_gumbel() {
    const uint32_t i = blockIdx.x * 256u + threadIdx.x;
    uint32_t o0, o1;
    threefry2x32_042(0u, i, o0, o1);
    const uint32_t bits = o0 ^ o1;
    float u = __uint_as_float((bits >> 9) | 0x3f800000u) - 1.0f;
    u = u * (1.0f - 1e-10f) + 1e-10f;
    u = fmaxf(1e-10f, u);
    g_gum[i] = -__logf(-__logf(u));
}

// ---------------- K0: zero column-sum accumulator ---------------------------
__global__ void k0_zero() {
    if (threadIdx.x < MSG) g_S[threadIdx.x] = 0.0f;
}

// ---------------- K1: h = relu(z@encW+b); msg = h@msgW+b; S += colsum -------
__global__ __launch_bounds__(256) void k1_enc(
    const float* __restrict__ z,
    const float* __restrict__ encW, const float* __restrict__ encb,
    const float* __restrict__ msgW, const float* __restrict__ msgb)
{
    __shared__ float  z_s[8 * LATENT];
    __shared__ float  h_s[8 * HID];
    __shared__ float2 m_s[8 * 32];

    const int t  = threadIdx.x;
    const int i0 = blockIdx.x * 8;

    reinterpret_cast<float4*>(z_s)[t] =
        reinterpret_cast<const float4*>(z + (size_t)i0 * LATENT)[t];
    __syncthreads();

    const int r = t >> 5, c = t & 31;

    float a = encb[c];
#pragma unroll 8
    for (int k = 0; k < LATENT; ++k)
        a = fmaf(z_s[r * LATENT + k], encW[k * HID + c], a);
    a = fmaxf(a, 0.0f);
    h_s[r * HID + c] = a;
    g_h[(size_t)(i0 + r) * HID + c] = a;
    __syncthreads();

    float2 m = make_float2(msgb[2 * c], msgb[2 * c + 1]);
#pragma unroll
    for (int k = 0; k < HID; ++k) {
        float hk = h_s[r * HID + k];
        float2 w = reinterpret_cast<const float2*>(msgW)[k * 32 + c];
        m.x = fmaf(hk, w.x, m.x);
        m.y = fmaf(hk, w.y, m.y);
    }
    reinterpret_cast<float2*>(g_msgF)[(size_t)(i0 + r) * 32 + c] = m;
    m_s[r * 32 + c] = m;
    __syncthreads();

    if (t < MSG) {
        float s = 0.0f;
#pragma unroll
        for (int rr = 0; rr < 8; ++rr) {
            float2 mm = m_s[rr * 32 + (t >> 1)];
            s += (t & 1) ? mm.y : mm.x;
        }
        atomicAdd(&g_S[t], s);
    }
}

// ---------------- K2: fail-sum partials, 2D grid (rowblk x colblk) ----------
// CTA = 64 rows x 512 cols. 16 warps, 4 rows/warp. Double-buffered msg tile.
__global__ __launch_bounds__(TPB2, 3) void k2_agg(const float* __restrict__ dists)
{
    extern __shared__ float msg_s[];          // 2 x 128*64 floats = 64KB

    const int tid  = threadIdx.x;
    const int wid  = tid >> 5;
    const int lane = tid & 31;
    const int rb   = blockIdx.x;              // 0..127
    const int cb   = blockIdx.y;              // 0..15
    const int row0 = rb * 64 + wid * 4;
    const int col0 = cb * COLB;

    const float* d0 = dists + (size_t)(row0 + 0) * NROW + col0 + lane * 4;
    const float* d1 = d0 + NROW;
    const float* d2 = d1 + NROW;
    const float* d3 = d2 + NROW;

    float2 acc[4];
#pragma unroll
    for (int r = 0; r < 4; ++r) acc[r] = make_float2(0.0f, 0.0f);

    const uint32_t sm0 = smem_u32(msg_s);

    // prefetch tile 0 into buffer 0
    {
        const float4* src = reinterpret_cast<const float4*>(g_msgF + (size_t)col0 * MSG);
#pragma unroll
        for (int q = 0; q < 4; ++q)
            CP_ASYNC16(sm0 + (tid + q * TPB2) * 16, src + tid + q * TPB2);
        CP_COMMIT();
    }

#pragma unroll 1
    for (int t = 0; t < NT; ++t) {
        const int s = t & 1;
        CP_WAIT0();
        __syncthreads();
        if (t + 1 < NT) {
            const uint32_t dst = sm0 + ((s ^ 1) * CTILE * MSG) * 4;
            const float4* src = reinterpret_cast<const float4*>(
                g_msgF + (size_t)(col0 + (t + 1) * CTILE) * MSG);
#pragma unroll
            for (int q = 0; q < 4; ++q)
                CP_ASYNC16(dst + (tid + q * TPB2) * 16, src + tid + q * TPB2);
            CP_COMMIT();
        }

        const float2* mf = reinterpret_cast<const float2*>(msg_s + s * CTILE * MSG) + lane;
        const int ofs = t * CTILE;

        // front-batch all 4 row loads (MLP=4) before any pop work
        const float4 dA = *reinterpret_cast<const float4*>(d0 + ofs);
        const float4 dB = *reinterpret_cast<const float4*>(d1 + ofs);
        const float4 dC = *reinterpret_cast<const float4*>(d2 + ofs);
        const float4 dD = *reinterpret_cast<const float4*>(d3 + ofs);

#define ROW_TILE(r, d4) { \
        unsigned m0 = __ballot_sync(0xffffffffu, d4.x >= THRESH);                     \
        unsigned m1 = __ballot_sync(0xffffffffu, d4.y >= THRESH);                     \
        unsigned m2 = __ballot_sync(0xffffffffu, d4.z >= THRESH);                     \
        unsigned m3 = __ballot_sync(0xffffffffu, d4.w >= THRESH);                     \
        while (m0) { int b = __ffs(m0) - 1; m0 &= m0 - 1;                             \
            float2 v = mf[(unsigned)(4 * b + 0) * 32u];                               \
            acc[r].x += v.x; acc[r].y += v.y; }                                       \
        while (m1) { int b = __ffs(m1) - 1; m1 &= m1 - 1;                             \
            float2 v = mf[(unsigned)(4 * b + 1) * 32u];                               \
            acc[r].x += v.x; acc[r].y += v.y; }                                       \
        while (m2) { int b = __ffs(m2) - 1; m2 &= m2 - 1;                             \
            float2 v = mf[(unsigned)(4 * b + 2) * 32u];                               \
            acc[r].x += v.x; acc[r].y += v.y; }                                       \
        while (m3) { int b = __ffs(m3) - 1; m3 &= m3 - 1;                             \
            float2 v = mf[(unsigned)(4 * b + 3) * 32u];                               \
            acc[r].x += v.x; acc[r].y += v.y; } }

        ROW_TILE(0, dA)
        ROW_TILE(1, dB)
        ROW_TILE(2, dC)
        ROW_TILE(3, dD)
#undef ROW_TILE
    }

    float2* gp = reinterpret_cast<float2*>(g_part) +
                 ((size_t)cb * NROW + row0) * 32 + lane;
#pragma unroll
    for (int r = 0; r < 4; ++r) gp[r * 32] = acc[r];
}

// ---------------- K3: combine partials + fused tail --------------------------
// 256 CTAs x 512 thr; 16 warps x 2 rows. Lane owns output cols (2l, 2l+1).
__global__ __launch_bounds__(TPB2) void k3_tail(
    const float* __restrict__ dists, const float* __restrict__ tau,
    const float* __restrict__ updW,  const float* __restrict__ updb,
    const float* __restrict__ outW,  const float* __restrict__ outb,
    float* __restrict__ out)
{
    const int wid  = threadIdx.x >> 5;
    const int lane = threadIdx.x & 31;
    const float itau = 1.0f / tau[0];
    const float S0 = g_S[2 * lane], S1 = g_S[2 * lane + 1];

#pragma unroll 1
    for (int rr = 0; rr < 2; ++rr) {
        const size_t row = (size_t)blockIdx.x * 32 + wid * 2 + rr;

        const float dii = dists[row * NROW + row];
        const float sub = (dii < THRESH) ? 1.0f : 0.0f;
        const float2 mi = reinterpret_cast<const float2*>(g_msgF)[row * 32 + lane];

        float a0 = S0 - sub * mi.x;
        float a1 = S1 - sub * mi.y;
#pragma unroll
        for (int p = 0; p < NCB; ++p) {
            const float2 pv = reinterpret_cast<const float2*>(g_part)
                [((size_t)p * NROW + row) * 32 + lane];
            a0 -= pv.x; a1 -= pv.y;
        }

        const float h_own = g_h[row * HID + lane];

        float acc2 = updb[lane];
#pragma unroll
        for (int k = 0; k < 32; ++k) {
            const float hk = __shfl_sync(0xffffffffu, h_own, k);
            const float src = (k & 1) ? a1 : a0;
            const float gA = __shfl_sync(0xffffffffu, src, k >> 1);
            const float gB = __shfl_sync(0xffffffffu, src, 16 + (k >> 1));
            acc2 = fmaf(hk, updW[k * HID + lane], acc2);
            acc2 = fmaf(gA, updW[(32 + k) * HID + lane], acc2);
            acc2 = fmaf(gB, updW[(64 + k) * HID + lane], acc2);
        }
        const float h2v = fmaxf(acc2, 0.0f);

        float2 lg = make_float2(outb[2 * lane], outb[2 * lane + 1]);
#pragma unroll
        for (int k = 0; k < 32; ++k) {
            const float h2k = __shfl_sync(0xffffffffu, h2v, k);
            const float2 w = reinterpret_cast<const float2*>(outW)[k * 32 + lane];
            lg.x = fmaf(h2k, w.x, lg.x);
            lg.y = fmaf(h2k, w.y, lg.y);
        }

        const float2 gum = reinterpret_cast<const float2*>(g_gum)[row * 32 + lane];
        const float v0 = (lg.x + gum.x) * itau;
        const float v1 = (lg.y + gum.y) * itau;

        float mx = fmaxf(v0, v1);
#pragma unroll
        for (int o = 16; o; o >>= 1) mx = fmaxf(mx, __shfl_xor_sync(0xffffffffu, mx, o));
        const float e0 = expf(v0 - mx), e1 = expf(v1 - mx);
        float sm = e0 + e1;
#pragma unroll
        for (int o = 16; o; o >>= 1) sm += __shfl_xor_sync(0xffffffffu, sm, o);
        const float inv = 1.0f / sm;

        reinterpret_cast<float2*>(out)[row * 32 + lane] = make_float2(e0 * inv, e1 * inv);
    }
}

// ---------------------------------------------------------------------------
extern "C" void kernel_launch(void* const* d_in, const int* in_sizes, int n_in,
                              void* d_out, int out_size) {
    const float* z    = (const float*)d_in[0];
    const float* tau  = (const float*)d_in[1];
    const float* dist = (const float*)d_in[2];
    const float* encW = (const float*)d_in[3];
    const float* encb = (const float*)d_in[4];
    const float* msgW = (const float*)d_in[5];
    const float* msgb = (const float*)d_in[6];
    const float* updW = (const float*)d_in[7];
    const float* updb = (const float*)d_in[8];
    const float* outW = (const float*)d_in[9];
    const float* outb = (const float*)d_in[10];
    float* out = (float*)d_out;

    const int smem2 = 2 * CTILE * MSG * (int)sizeof(float);   // 64 KB
    cudaFuncSetAttribute(k2_agg, cudaFuncAttributeMaxDynamicSharedMemorySize, smem2);

    k0_zero<<<1, 64>>>();
    k1_enc<<<NROW / 8, 256>>>(z, encW, encb, msgW, msgb);
    kg_gumbel<<<(NROW * MSG) / 256, 256>>>();

    dim3 g2(NROW / 64, NCB);
    k2_agg<<<g2, TPB2, smem2>>>(dist);

    k3_tail<<<NROW / 32, TPB2>>>(dist, tau, updW, updb, outW, outb, out);
}

// round 5
// speedup vs baseline: 2.6996x; 1.1290x over previous
#include <cuda_runtime.h>
#include <cstdint>

#define NROW 8192
#define LATENT 128
#define HID 32
#define MSG 64
#define THRESH 1.5f

#define NCB 16                // column blocks
#define COLB (NROW / NCB)     // 512 cols per CTA
#define CTILE 128             // cols per smem tile
#define NT (COLB / CTILE)     // 4 tiles
#define TPB2 512

// ---------------- device scratch (no allocation allowed) -------------------
__device__ __align__(16) float g_h[NROW * HID];          // 1 MB
__device__ __align__(16) float g_msgF[NROW * MSG];       // 2 MB row-major
__device__ __align__(16) float g_part[NCB * NROW * MSG]; // 32 MB fail-sum partials
__device__ float g_S[MSG];                               // column sums of messages

// ---------------- asm helpers -----------------------------------------------
__device__ __forceinline__ uint32_t smem_u32(const void* p) {
    uint32_t a;
    asm("{ .reg .u64 t; cvta.to.shared.u64 t, %1; cvt.u32.u64 %0, t; }" : "=r"(a) : "l"(p));
    return a;
}
#define CP_ASYNC16(sm, gp) \
    asm volatile("cp.async.cg.shared.global [%0], [%1], 16;" :: "r"(sm), "l"(gp) : "memory")
#define CP_COMMIT() asm volatile("cp.async.commit_group;" ::: "memory")
#define CP_WAIT0()  asm volatile("cp.async.wait_group 0;" ::: "memory")

// packed fp32x2 add (Blackwell): acc += v in one instruction
__device__ __forceinline__ void fadd2(uint64_t& a, uint64_t v) {
    asm("add.rn.f32x2 %0, %0, %1;" : "+l"(a) : "l"(v));
}

// ---------------- threefry / gumbel ----------------------------------------
__device__ __forceinline__ uint32_t rotl32(uint32_t x, int r) { return __funnelshift_l(x, x, r); }
__device__ __forceinline__ void threefry2x32_042(uint32_t x0, uint32_t x1,
                                                 uint32_t& o0, uint32_t& o1) {
    const uint32_t k0 = 0u, k1 = 42u, k2 = 0u ^ 42u ^ 0x1BD11BDAu;
    x0 += k0; x1 += k1;
#define TF_RND(r) { x0 += x1; x1 = rotl32(x1, r); x1 ^= x0; }
    TF_RND(13) TF_RND(15) TF_RND(26) TF_RND(6)
    x0 += k1; x1 += k2 + 1u;
    TF_RND(17) TF_RND(29) TF_RND(16) TF_RND(24)
    x0 += k2; x1 += k0 + 2u;
    TF_RND(13) TF_RND(15) TF_RND(26) TF_RND(6)
    x0 += k0; x1 += k1 + 3u;
    TF_RND(17) TF_RND(29) TF_RND(16) TF_RND(24)
    x0 += k1; x1 += k2 + 4u;
    TF_RND(13) TF_RND(15) TF_RND(26) TF_RND(6)
    x0 += k2; x1 += k0 + 5u;
#undef TF_RND
    o0 = x0; o1 = x1;
}
__device__ __forceinline__ float gumbel_at(uint32_t i) {
    uint32_t o0, o1;
    threefry2x32_042(0u, i, o0, o1);
    const uint32_t bits = o0 ^ o1;
    float u = __uint_as_float((bits >> 9) | 0x3f800000u) - 1.0f;
    u = u * (1.0f - 1e-10f) + 1e-10f;
    u = fmaxf(1e-10f, u);
    return -__logf(-__logf(u));
}

// ---------------- K0: zero column-sum accumulator ---------------------------
__global__ void k0_zero() {
    if (threadIdx.x < MSG) g_S[threadIdx.x] = 0.0f;
}

// ---------------- K1: h = relu(z@encW+b); msg = h@msgW+b; S += colsum -------
__global__ __launch_bounds__(256) void k1_enc(
    const float* __restrict__ z,
    const float* __restrict__ encW, const float* __restrict__ encb,
    const float* __restrict__ msgW, const float* __restrict__ msgb)
{
    __shared__ float  z_s[8 * LATENT];
    __shared__ float  h_s[8 * HID];
    __shared__ float2 m_s[8 * 32];

    const int t  = threadIdx.x;
    const int i0 = blockIdx.x * 8;

    reinterpret_cast<float4*>(z_s)[t] =
        reinterpret_cast<const float4*>(z + (size_t)i0 * LATENT)[t];
    __syncthreads();

    const int r = t >> 5, c = t & 31;

    float a = encb[c];
#pragma unroll 8
    for (int k = 0; k < LATENT; ++k)
        a = fmaf(z_s[r * LATENT + k], encW[k * HID + c], a);
    a = fmaxf(a, 0.0f);
    h_s[r * HID + c] = a;
    g_h[(size_t)(i0 + r) * HID + c] = a;
    __syncthreads();

    float2 m = make_float2(msgb[2 * c], msgb[2 * c + 1]);
#pragma unroll
    for (int k = 0; k < HID; ++k) {
        float hk = h_s[r * HID + k];
        float2 w = reinterpret_cast<const float2*>(msgW)[k * 32 + c];
        m.x = fmaf(hk, w.x, m.x);
        m.y = fmaf(hk, w.y, m.y);
    }
    reinterpret_cast<float2*>(g_msgF)[(size_t)(i0 + r) * 32 + c] = m;
    m_s[r * 32 + c] = m;
    __syncthreads();

    if (t < MSG) {
        float s = 0.0f;
#pragma unroll
        for (int rr = 0; rr < 8; ++rr) {
            float2 mm = m_s[rr * 32 + (t >> 1)];
            s += (t & 1) ? mm.y : mm.x;
        }
        atomicAdd(&g_S[t], s);
    }
}

// ---------------- K2: fail-sum partials, 2D grid (rowblk x colblk) ----------
// CTA = 64 rows x 512 cols. 16 warps, 4 rows/warp. Double-buffered msg tile.
__global__ __launch_bounds__(TPB2, 3) void k2_agg(const float* __restrict__ dists)
{
    extern __shared__ float msg_s[];          // 2 x 128*64 floats = 64KB

    const int tid  = threadIdx.x;
    const int wid  = tid >> 5;
    const int lane = tid & 31;
    const int rb   = blockIdx.x;              // 0..127
    const int cb   = blockIdx.y;              // 0..15
    const int row0 = rb * 64 + wid * 4;
    const int col0 = cb * COLB;

    const float* d0 = dists + (size_t)(row0 + 0) * NROW + col0 + lane * 4;
    const float* d1 = d0 + NROW;
    const float* d2 = d1 + NROW;
    const float* d3 = d2 + NROW;

    uint64_t acc[4] = {0ull, 0ull, 0ull, 0ull};   // packed f32x2 accumulators

    const uint32_t sm0 = smem_u32(msg_s);

    // prefetch tile 0 into buffer 0
    {
        const float4* src = reinterpret_cast<const float4*>(g_msgF + (size_t)col0 * MSG);
#pragma unroll
        for (int q = 0; q < 4; ++q)
            CP_ASYNC16(sm0 + (tid + q * TPB2) * 16, src + tid + q * TPB2);
        CP_COMMIT();
    }

#pragma unroll 1
    for (int t = 0; t < NT; ++t) {
        const int s = t & 1;
        CP_WAIT0();
        __syncthreads();
        if (t + 1 < NT) {
            const uint32_t dst = sm0 + ((s ^ 1) * CTILE * MSG) * 4;
            const float4* src = reinterpret_cast<const float4*>(
                g_msgF + (size_t)(col0 + (t + 1) * CTILE) * MSG);
#pragma unroll
            for (int q = 0; q < 4; ++q)
                CP_ASYNC16(dst + (tid + q * TPB2) * 16, src + tid + q * TPB2);
            CP_COMMIT();
        }

        // smem base for this stage: lane's float2 slot within a msg row
        const char* ms = reinterpret_cast<const char*>(msg_s)
                       + s * (CTILE * MSG * 4) + lane * 8;
        const int ofs = t * CTILE;

        // front-batch all 4 row loads (MLP=4), streaming (evict-first)
        const float4 dA = __ldcs(reinterpret_cast<const float4*>(d0 + ofs));
        const float4 dB = __ldcs(reinterpret_cast<const float4*>(d1 + ofs));
        const float4 dC = __ldcs(reinterpret_cast<const float4*>(d2 + ofs));
        const float4 dD = __ldcs(reinterpret_cast<const float4*>(d3 + ofs));

#define ROW_TILE(r, d4) { \
        unsigned m0 = __ballot_sync(0xffffffffu, d4.x >= THRESH);                     \
        unsigned m1 = __ballot_sync(0xffffffffu, d4.y >= THRESH);                     \
        unsigned m2 = __ballot_sync(0xffffffffu, d4.z >= THRESH);                     \
        unsigned m3 = __ballot_sync(0xffffffffu, d4.w >= THRESH);                     \
        while (m0) { int b = __ffs(m0) - 1; m0 &= m0 - 1;                             \
            fadd2(acc[r], *reinterpret_cast<const uint64_t*>(ms + 0 * 256 + b * 1024)); } \
        while (m1) { int b = __ffs(m1) - 1; m1 &= m1 - 1;                             \
            fadd2(acc[r], *reinterpret_cast<const uint64_t*>(ms + 1 * 256 + b * 1024)); } \
        while (m2) { int b = __ffs(m2) - 1; m2 &= m2 - 1;                             \
            fadd2(acc[r], *reinterpret_cast<const uint64_t*>(ms + 2 * 256 + b * 1024)); } \
        while (m3) { int b = __ffs(m3) - 1; m3 &= m3 - 1;                             \
            fadd2(acc[r], *reinterpret_cast<const uint64_t*>(ms + 3 * 256 + b * 1024)); } }

        ROW_TILE(0, dA)
        ROW_TILE(1, dB)
        ROW_TILE(2, dC)
        ROW_TILE(3, dD)
#undef ROW_TILE
    }

    uint64_t* gp = reinterpret_cast<uint64_t*>(g_part) +
                   ((size_t)cb * NROW + row0) * 32 + lane;
#pragma unroll
    for (int r = 0; r < 4; ++r) gp[r * 32] = acc[r];
}

// ---------------- K3: combine partials + gumbel + fused tail -----------------
// 512 CTAs x 512 thr; 16 warps x 1 row. Lane owns output cols (2l, 2l+1).
__global__ __launch_bounds__(TPB2) void k3_tail(
    const float* __restrict__ dists, const float* __restrict__ tau,
    const float* __restrict__ updW,  const float* __restrict__ updb,
    const float* __restrict__ outW,  const float* __restrict__ outb,
    float* __restrict__ out)
{
    const int wid  = threadIdx.x >> 5;
    const int lane = threadIdx.x & 31;
    const float itau = 1.0f / tau[0];

    const size_t row = (size_t)blockIdx.x * 16 + wid;

    // front-batch independent loads
    const float2 Sv = reinterpret_cast<const float2*>(g_S)[lane];
    const float dii = dists[row * NROW + row];
    const float2 mi = reinterpret_cast<const float2*>(g_msgF)[row * 32 + lane];
    const float h_own = g_h[row * HID + lane];

    float a0 = Sv.x, a1 = Sv.y;
#pragma unroll
    for (int p = 0; p < NCB; ++p) {
        const float2 pv = reinterpret_cast<const float2*>(g_part)
            [((size_t)p * NROW + row) * 32 + lane];
        a0 -= pv.x; a1 -= pv.y;
    }
    const float sub = (dii < THRESH) ? 1.0f : 0.0f;
    a0 -= sub * mi.x;
    a1 -= sub * mi.y;

    // gumbel for this row's two columns (computed inline, overlaps loads above)
    const uint32_t gi = (uint32_t)row * 64u + 2u * lane;
    const float gum0 = gumbel_at(gi);
    const float gum1 = gumbel_at(gi + 1);

    float acc2 = updb[lane];
#pragma unroll
    for (int k = 0; k < 32; ++k) {
        const float hk = __shfl_sync(0xffffffffu, h_own, k);
        const float src = (k & 1) ? a1 : a0;
        const float gA = __shfl_sync(0xffffffffu, src, k >> 1);
        const float gB = __shfl_sync(0xffffffffu, src, 16 + (k >> 1));
        acc2 = fmaf(hk, updW[k * HID + lane], acc2);
        acc2 = fmaf(gA, updW[(32 + k) * HID + lane], acc2);
        acc2 = fmaf(gB, updW[(64 + k) * HID + lane], acc2);
    }
    const float h2v = fmaxf(acc2, 0.0f);

    float2 lg = make_float2(outb[2 * lane], outb[2 * lane + 1]);
#pragma unroll
    for (int k = 0; k < 32; ++k) {
        const float h2k = __shfl_sync(0xffffffffu, h2v, k);
        const float2 w = reinterpret_cast<const float2*>(outW)[k * 32 + lane];
        lg.x = fmaf(h2k, w.x, lg.x);
        lg.y = fmaf(h2k, w.y, lg.y);
    }

    const float v0 = (lg.x + gum0) * itau;
    const float v1 = (lg.y + gum1) * itau;

    float mx = fmaxf(v0, v1);
#pragma unroll
    for (int o = 16; o; o >>= 1) mx = fmaxf(mx, __shfl_xor_sync(0xffffffffu, mx, o));
    const float e0 = expf(v0 - mx), e1 = expf(v1 - mx);
    float sm = e0 + e1;
#pragma unroll
    for (int o = 16; o; o >>= 1) sm += __shfl_xor_sync(0xffffffffu, sm, o);
    const float inv = 1.0f / sm;

    reinterpret_cast<float2*>(out)[row * 32 + lane] = make_float2(e0 * inv, e1 * inv);
}

// ---------------------------------------------------------------------------
extern "C" void kernel_launch(void* const* d_in, const int* in_sizes, int n_in,
                              void* d_out, int out_size) {
    const float* z    = (const float*)d_in[0];
    const float* tau  = (const float*)d_in[1];
    const float* dist = (const float*)d_in[2];
    const float* encW = (const float*)d_in[3];
    const float* encb = (const float*)d_in[4];
    const float* msgW = (const float*)d_in[5];
    const float* msgb = (const float*)d_in[6];
    const float* updW = (const float*)d_in[7];
    const float* updb = (const float*)d_in[8];
    const float* outW = (const float*)d_in[9];
    const float* outb = (const float*)d_in[10];
    float* out = (float*)d_out;

    const int smem2 = 2 * CTILE * MSG * (int)sizeof(float);   // 64 KB
    cudaFuncSetAttribute(k2_agg, cudaFuncAttributeMaxDynamicSharedMemorySize, smem2);

    k0_zero<<<1, 64>>>();
    k1_enc<<<NROW / 8, 256>>>(z, encW, encb, msgW, msgb);

    dim3 g2(NROW / 64, NCB);
    k2_agg<<<g2, TPB2, smem2>>>(dist);

    k3_tail<<<NROW / 16, TPB2>>>(dist, tau, updW, updb, outW, outb, out);
}